// round 1
// baseline (speedup 1.0000x reference)
#include <cuda_runtime.h>

// Router: logits = x @ wg^T + gr @ gm^T ; std-normalized softmax; top-2;
// mask expert E-1; renormalize.
// Output layout (float32): [gates 2T | indices 2T | logits 8T]

constexpr int D       = 2048;
constexpr int E       = 8;
constexpr int NT      = 4;            // tokens per warp (register-blocked)
constexpr int THREADS = 256;
constexpr int WARPS   = THREADS / 32;
constexpr int CHUNKS  = D / 4;        // 16B chunks per row = 512
constexpr int ITERS   = CHUNKS / 32;  // 16 per-lane iterations
constexpr int SMEM_BYTES = (E * D + 64) * 4;   // wg + gm = 65792 B
constexpr int GRID    = 256;

__device__ __forceinline__ unsigned long long ffma2(unsigned long long a,
                                                    unsigned long long b,
                                                    unsigned long long c) {
    unsigned long long d;
    asm("fma.rn.f32x2 %0, %1, %2, %3;" : "=l"(d) : "l"(a), "l"(b), "l"(c));
    return d;
}

__device__ __forceinline__ float pairsum(unsigned long long v) {
    float2 f;
    f.x = __uint_as_float((unsigned int)(v & 0xffffffffull));
    f.y = __uint_as_float((unsigned int)(v >> 32));
    return f.x + f.y;
}

__global__ void __launch_bounds__(THREADS, 2)
router_kernel(const float* __restrict__ x,
              const float* __restrict__ wg,
              const float* __restrict__ gm,
              const float* __restrict__ gr,
              float* __restrict__ out_gates,
              float* __restrict__ out_idx,
              float* __restrict__ out_logits,
              int nGroups) {
    extern __shared__ float smem[];
    float4* s_wg4 = reinterpret_cast<float4*>(smem);           // [E][D] floats
    float*  s_gm  = smem + E * D;                               // [E][E]

    // Stage wg + gm into shared once per CTA.
    const float4* wg4 = reinterpret_cast<const float4*>(wg);
    for (int i = threadIdx.x; i < E * CHUNKS; i += THREADS) s_wg4[i] = wg4[i];
    if (threadIdx.x < E * E) s_gm[threadIdx.x] = gm[threadIdx.x];
    __syncthreads();

    const ulonglong2* s_w2 = reinterpret_cast<const ulonglong2*>(smem);

    const int lane     = threadIdx.x & 31;
    const int gwarp    = blockIdx.x * WARPS + (threadIdx.x >> 5);
    const int totWarps = gridDim.x * WARPS;

    for (int g = gwarp; g < nGroups; g += totWarps) {
        const int t0 = g * NT;

        unsigned long long acc[NT][E];
        #pragma unroll
        for (int j = 0; j < NT; j++)
            #pragma unroll
            for (int e = 0; e < E; e++) acc[j][e] = 0ull;

        const ulonglong2* xr[NT];
        #pragma unroll
        for (int j = 0; j < NT; j++)
            xr[j] = reinterpret_cast<const ulonglong2*>(x + (size_t)(t0 + j) * D);

        #pragma unroll 4
        for (int it = 0; it < ITERS; it++) {
            const int c = it * 32 + lane;           // 16B-chunk index in row
            ulonglong2 xv[NT];
            #pragma unroll
            for (int j = 0; j < NT; j++) xv[j] = xr[j][c];
            #pragma unroll
            for (int e = 0; e < E; e++) {
                ulonglong2 wv = s_w2[e * CHUNKS + c];
                #pragma unroll
                for (int j = 0; j < NT; j++) {
                    acc[j][e] = ffma2(xv[j].x, wv.x, acc[j][e]);
                    acc[j][e] = ffma2(xv[j].y, wv.y, acc[j][e]);
                }
            }
        }

        // Butterfly reduction: every lane ends with the full dot products.
        float red[NT][E];
        #pragma unroll
        for (int j = 0; j < NT; j++) {
            #pragma unroll
            for (int e = 0; e < E; e++) {
                float s = pairsum(acc[j][e]);
                #pragma unroll
                for (int off = 16; off > 0; off >>= 1)
                    s += __shfl_xor_sync(0xffffffffu, s, off);
                red[j][e] = s;
            }
        }

        // Lane j (< NT) owns token t0+j. Select its row statically.
        float logit[E];
        #pragma unroll
        for (int e = 0; e < E; e++) {
            float v = red[0][e];
            if (lane == 1) v = red[1][e];
            if (lane == 2) v = red[2][e];
            if (lane == 3) v = red[3][e];
            logit[e] = v;
        }

        if (lane < NT) {
            const int t = t0 + lane;

            // gate_map residual: logit[f] += sum_e gr[t][e] * gm[f][e]
            float4 g0 = *reinterpret_cast<const float4*>(gr + (size_t)t * E);
            float4 g1 = *reinterpret_cast<const float4*>(gr + (size_t)t * E + 4);
            float grv[8] = {g0.x, g0.y, g0.z, g0.w, g1.x, g1.y, g1.z, g1.w};
            float lg[E];
            #pragma unroll
            for (int f = 0; f < E; f++) {
                float s = logit[f];
                #pragma unroll
                for (int e = 0; e < E; e++) s = fmaf(grv[e], s_gm[f * E + e], s);
                lg[f] = s;
            }

            // unbiased std (ddof=1) over E=8
            float mean = 0.f;
            #pragma unroll
            for (int f = 0; f < E; f++) mean += lg[f];
            mean *= (1.f / E);
            float var = 0.f;
            #pragma unroll
            for (int f = 0; f < E; f++) {
                float d = lg[f] - mean;
                var = fmaf(d, d, var);
            }
            float inv_std = rsqrtf(var * (1.f / (E - 1)));

            // softmax(lg * inv_std)
            float z[E], m = -3.402823466e+38f;
            #pragma unroll
            for (int f = 0; f < E; f++) {
                z[f] = lg[f] * inv_std;
                m = fmaxf(m, z[f]);
            }
            float p[E], psum = 0.f;
            #pragma unroll
            for (int f = 0; f < E; f++) {
                p[f] = __expf(z[f] - m);
                psum += p[f];
            }
            float inv_psum = 1.f / psum;
            #pragma unroll
            for (int f = 0; f < E; f++) p[f] *= inv_psum;

            // stable top-2 (descending, lower index wins ties)
            int i1 = 0; float v1 = p[0];
            #pragma unroll
            for (int f = 1; f < E; f++)
                if (p[f] > v1) { v1 = p[f]; i1 = f; }
            int i2; float v2;
            if (i1 == 0) { i2 = 1; v2 = p[1]; } else { i2 = 0; v2 = p[0]; }
            #pragma unroll
            for (int f = 1; f < E; f++)
                if (f != i1 && p[f] > v2) { v2 = p[f]; i2 = f; }

            // mask last expert, renormalize over the 2 selected
            float gg1 = (i1 == E - 1) ? 0.f : v1;
            float gg2 = (i2 == E - 1) ? 0.f : v2;
            float inv_s = 1.f / (gg1 + gg2);
            gg1 *= inv_s; gg2 *= inv_s;

            float2 gpair; gpair.x = gg1; gpair.y = gg2;
            *reinterpret_cast<float2*>(out_gates + (size_t)2 * t) = gpair;
            float2 ipair; ipair.x = (float)i1; ipair.y = (float)i2;
            *reinterpret_cast<float2*>(out_idx + (size_t)2 * t) = ipair;

            float4 L0; L0.x = lg[0]; L0.y = lg[1]; L0.z = lg[2]; L0.w = lg[3];
            float4 L1; L1.x = lg[4]; L1.y = lg[5]; L1.z = lg[6]; L1.w = lg[7];
            float4* olr = reinterpret_cast<float4*>(out_logits + (size_t)t * E);
            olr[0] = L0;
            olr[1] = L1;
        }
    }
}

extern "C" void kernel_launch(void* const* d_in, const int* in_sizes, int n_in,
                              void* d_out, int out_size) {
    const float* x  = (const float*)d_in[0];   // [T, D]
    const float* wg = (const float*)d_in[1];   // [E, D]
    const float* gm = (const float*)d_in[2];   // [E, E]
    const float* gr = (const float*)d_in[3];   // [T, E]

    const int T = in_sizes[0] / D;
    float* out       = (float*)d_out;
    float* out_gates = out;                       // [T,2]
    float* out_idx   = out + (size_t)2 * T;       // [T,2] as float
    float* out_logit = out + (size_t)4 * T;       // [T,8]

    cudaFuncSetAttribute(router_kernel,
                         cudaFuncAttributeMaxDynamicSharedMemorySize,
                         SMEM_BYTES);

    const int nGroups = T / NT;
    router_kernel<<<GRID, THREADS, SMEM_BYTES>>>(x, wg, gm, gr,
                                                 out_gates, out_idx, out_logit,
                                                 nGroups);
}